// round 12
// baseline (speedup 1.0000x reference)
#include <cuda_runtime.h>
#include <cuda_bf16.h>
#include <cstdint>

#define NN 100000
#define NP 100096              // 782 * 128 (padded rows)
#define DD 128
#define EE 1600000
#define ND (NN * DD)
#define MBLK 782               // row blocks

// ---------------- scratch (__device__ globals; zero-initialized) ----------------
__device__ float g_h[NP * DD];
__device__ float g_m[NP * DD];
__device__ float g_agg[NP * DD];
__device__ float g_gi[NP * 384];
__device__ __nv_bfloat16 g_h_hi[NP * DD], g_h_lo[NP * DD];
__device__ __nv_bfloat16 g_agg_hi[NP * DD], g_agg_lo[NP * DD];
__device__ __nv_bfloat16 g_Wih_hi[384 * 128], g_Wih_lo[384 * 128];
__device__ __nv_bfloat16 g_Whh_hi[384 * 128], g_Whh_lo[384 * 128];
__device__ __nv_bfloat16 g_Wt_hi[128 * 128], g_Wt_lo[128 * 128];
__device__ int g_src[EE];
__device__ int g_dst[EE];
__device__ int g_is64;

// ---------------- warp MMA helpers (base-target PTX: sm_80+ features only) ----------------
__device__ __forceinline__ uint32_t smem_u32(const void* p) {
    uint32_t a;
    asm("{ .reg .u64 t; cvta.to.shared.u64 t, %1; cvt.u32.u64 %0, t; }" : "=r"(a) : "l"(p));
    return a;
}
__device__ __forceinline__ void ldsm4(uint32_t r[4], uint32_t addr) {
    asm volatile("ldmatrix.sync.aligned.m8n8.x4.shared.b16 {%0,%1,%2,%3}, [%4];"
        : "=r"(r[0]), "=r"(r[1]), "=r"(r[2]), "=r"(r[3]) : "r"(addr));
}
__device__ __forceinline__ void mma16816(float c[4], const uint32_t a[4], uint32_t b0, uint32_t b1) {
    asm volatile("mma.sync.aligned.m16n8k16.row.col.f32.bf16.bf16.f32 "
        "{%0,%1,%2,%3}, {%4,%5,%6,%7}, {%8,%9}, {%0,%1,%2,%3};"
        : "+f"(c[0]), "+f"(c[1]), "+f"(c[2]), "+f"(c[3])
        : "r"(a[0]), "r"(a[1]), "r"(a[2]), "r"(a[3]), "r"(b0), "r"(b1));
}
__device__ __forceinline__ float sigm(float x) { return 1.f / (1.f + expf(-x)); }

// chunk layouts: [128 rows][40 bf16] (80B stride, 16B-aligned, conflict-free ldmatrix)
#define CPAD 40
// smem offsets for m/gi kernels
#define SA_HI 0
#define SA_LO 10240
#define SB_HI 20480
#define SB_LO 30720
#define SSTG  40960
#define SMEM_G (40960 + 128 * 129 * 4)     // 107008

// load one 128x32 bf16 chunk (row-major src, stride 128) into padded smem
__device__ __forceinline__ void ld_chunk(char* smem, int dst, const __nv_bfloat16* __restrict__ src,
                                         int kc, int tid) {
#pragma unroll
    for (int t = 0; t < 2; t++) {
        int lin = tid + 256 * t;          // 0..511
        int row = lin >> 2;
        int kq = (lin & 3) * 8;
        *(uint4*)(smem + dst + row * (CPAD * 2) + kq * 2) =
            *(const uint4*)(src + (size_t)row * 128 + kc + kq);
    }
}

// A-fragment ldmatrix address helpers (within chunk / tile)
__device__ __forceinline__ void frag_a(uint32_t a[4], uint32_t base_addr, int stride_bf16,
                                       int row0, int k, int lane) {
    int row = row0 + (lane & 15);
    int kk = k + ((lane >> 4) << 3);
    ldsm4(a, base_addr + (row * stride_bf16 + kk) * 2);
}
// B fragment: fills b0,b1 (n-tile j) and b2,b3 (n-tile j+1) for 16 consecutive n
__device__ __forceinline__ void frag_b(uint32_t b[4], uint32_t base_addr, int stride_bf16,
                                       int n0, int k, int lane) {
    int n = n0 + (lane & 7) + ((lane >> 4) & 1) * 8;
    int kk = k + (((lane >> 3) & 1) << 3);
    ldsm4(b, base_addr + (n * stride_bf16 + kk) * 2);
}

// core 128x128x128 accumulate: A,B global bf16 row-major (stride 128), acc += A@B^T
__device__ __forceinline__ void gemm_core(char* smem, float c[4][4][4],
                                          const __nv_bfloat16* Ah, const __nv_bfloat16* Al,
                                          const __nv_bfloat16* Bh, const __nv_bfloat16* Bl,
                                          int tid, int wm, int wn, int lane) {
    uint32_t sb = smem_u32(smem);
    for (int ch = 0; ch < 4; ch++) {
        int kc = ch * 32;
        __syncthreads();
        ld_chunk(smem, SA_HI, Ah, kc, tid);
        ld_chunk(smem, SA_LO, Al, kc, tid);
        ld_chunk(smem, SB_HI, Bh, kc, tid);
        ld_chunk(smem, SB_LO, Bl, kc, tid);
        __syncthreads();
#pragma unroll
        for (int k16 = 0; k16 < 32; k16 += 16) {
            uint32_t ah[4][4], al[4][4], bh[2][4], bl[2][4];
#pragma unroll
            for (int i = 0; i < 4; i++) {
                frag_a(ah[i], sb + SA_HI, CPAD, wm * 64 + i * 16, k16, lane);
                frag_a(al[i], sb + SA_LO, CPAD, wm * 64 + i * 16, k16, lane);
            }
#pragma unroll
            for (int j = 0; j < 2; j++) {
                frag_b(bh[j], sb + SB_HI, CPAD, wn * 32 + j * 16, k16, lane);
                frag_b(bl[j], sb + SB_LO, CPAD, wn * 32 + j * 16, k16, lane);
            }
#pragma unroll
            for (int i = 0; i < 4; i++)
#pragma unroll
                for (int j = 0; j < 4; j++) {
                    uint32_t B0h = bh[j >> 1][(j & 1) * 2], B1h = bh[j >> 1][(j & 1) * 2 + 1];
                    uint32_t B0l = bl[j >> 1][(j & 1) * 2], B1l = bl[j >> 1][(j & 1) * 2 + 1];
                    mma16816(c[i][j], ah[i], B0h, B1h);
                    mma16816(c[i][j], al[i], B0h, B1h);
                    mma16816(c[i][j], ah[i], B0l, B1l);
                }
        }
    }
}

// stage c-frags into padded smem stage [128][129]
__device__ __forceinline__ void stage_c(float* stg, float c[4][4][4], int wm, int wn, int lane) {
#pragma unroll
    for (int i = 0; i < 4; i++)
#pragma unroll
        for (int j = 0; j < 4; j++) {
            int m = wm * 64 + i * 16 + (lane >> 2);
            int col = wn * 32 + j * 8 + (lane & 3) * 2;
            stg[m * 129 + col]       = c[i][j][0];
            stg[m * 129 + col + 1]   = c[i][j][1];
            stg[(m + 8) * 129 + col]     = c[i][j][2];
            stg[(m + 8) * 129 + col + 1] = c[i][j][3];
        }
}

// ---------------- m = h @ W_l^T ----------------
__global__ __launch_bounds__(256) void mgemm_kernel() {
    extern __shared__ char smem[];
    int tid = threadIdx.x, wid = tid >> 5, lane = tid & 31;
    int wm = wid & 1, wn = wid >> 1;
    int m0 = blockIdx.x * 128;
    float c[4][4][4];
#pragma unroll
    for (int i = 0; i < 4; i++)
#pragma unroll
        for (int j = 0; j < 4; j++)
#pragma unroll
            for (int p = 0; p < 4; p++) c[i][j][p] = 0.f;

    gemm_core(smem, c, g_h_hi + (size_t)m0 * 128, g_h_lo + (size_t)m0 * 128,
              g_Wt_hi, g_Wt_lo, tid, wm, wn, lane);

    float* stg = (float*)(smem + SSTG);
    stage_c(stg, c, wm, wn, lane);
    __syncthreads();
#pragma unroll
    for (int it = 0; it < 64; it++) {
        int idx = tid + 256 * it;
        int row = idx >> 7, col = idx & 127;
        g_m[((size_t)m0 + row) * 128 + col] = stg[row * 129 + col];
    }
}

// ---------------- gi = agg @ W_ih^T + b_ih ----------------
__global__ __launch_bounds__(256) void gi_kernel(const float* __restrict__ b_ih) {
    extern __shared__ char smem[];
    int tid = threadIdx.x, wid = tid >> 5, lane = tid & 31;
    int wm = wid & 1, wn = wid >> 1;
    int m0 = blockIdx.x * 128;
    int bb = blockIdx.y;                      // gate block 0..2
    float c[4][4][4];
#pragma unroll
    for (int i = 0; i < 4; i++)
#pragma unroll
        for (int j = 0; j < 4; j++)
#pragma unroll
            for (int p = 0; p < 4; p++) c[i][j][p] = 0.f;

    gemm_core(smem, c, g_agg_hi + (size_t)m0 * 128, g_agg_lo + (size_t)m0 * 128,
              g_Wih_hi + bb * 128 * 128, g_Wih_lo + bb * 128 * 128, tid, wm, wn, lane);

    float* stg = (float*)(smem + SSTG);
    stage_c(stg, c, wm, wn, lane);
    __syncthreads();
#pragma unroll
    for (int it = 0; it < 64; it++) {
        int idx = tid + 256 * it;
        int row = idx >> 7, col = idx & 127;
        g_gi[((size_t)m0 + row) * 384 + bb * 128 + col] = stg[row * 129 + col] + __ldg(&b_ih[bb * 128 + col]);
    }
}

// ---------------- fused gh + GRU: h_new = GRU(gi, h@W_hh^T + b_hh, h) ----------------
// smem: A tile (h hi/lo, full K=128, stride 136) + B chunk + r/z stages
#define BA_HI 0
#define BA_LO 34816
#define BB_HI 69632
#define BB_LO 79872
#define BSTR  90112
#define BSTZ  156160
#define SMEM_B2 222208

__global__ __launch_bounds__(256) void ghgru_kernel(const float* __restrict__ b_hh) {
    extern __shared__ char smem[];
    uint32_t sb = smem_u32(smem);
    int tid = threadIdx.x, wid = tid >> 5, lane = tid & 31;
    int wm = wid & 1, wn = wid >> 1;
    int m0 = blockIdx.x * 128;
    float* str_ = (float*)(smem + BSTR);
    float* stz_ = (float*)(smem + BSTZ);

    // cache full h tile (hi/lo) in smem, stride 136 bf16
#pragma unroll
    for (int it = 0; it < 8; it++) {
        int lin = tid + 256 * it;
        int row = lin >> 4;
        int kq = (lin & 15) * 8;
        *(uint4*)(smem + BA_HI + row * 272 + kq * 2) = *(const uint4*)(g_h_hi + ((size_t)m0 + row) * 128 + kq);
        *(uint4*)(smem + BA_LO + row * 272 + kq * 2) = *(const uint4*)(g_h_lo + ((size_t)m0 + row) * 128 + kq);
    }

    for (int b = 0; b < 3; b++) {
        float c[4][4][4];
#pragma unroll
        for (int i = 0; i < 4; i++)
#pragma unroll
            for (int j = 0; j < 4; j++)
#pragma unroll
                for (int p = 0; p < 4; p++) c[i][j][p] = 0.f;

        for (int ch = 0; ch < 4; ch++) {
            int kc = ch * 32;
            __syncthreads();
            ld_chunk(smem, BB_HI, g_Whh_hi + (size_t)(b * 128) * 128, kc, tid);
            ld_chunk(smem, BB_LO, g_Whh_lo + (size_t)(b * 128) * 128, kc, tid);
            __syncthreads();
#pragma unroll
            for (int k16 = 0; k16 < 32; k16 += 16) {
                uint32_t ah[4][4], al[4][4], bh[2][4], bl[2][4];
#pragma unroll
                for (int i = 0; i < 4; i++) {
                    frag_a(ah[i], sb + BA_HI, 136, wm * 64 + i * 16, kc + k16, lane);
                    frag_a(al[i], sb + BA_LO, 136, wm * 64 + i * 16, kc + k16, lane);
                }
#pragma unroll
                for (int j = 0; j < 2; j++) {
                    frag_b(bh[j], sb + BB_HI, CPAD, wn * 32 + j * 16, k16, lane);
                    frag_b(bl[j], sb + BB_LO, CPAD, wn * 32 + j * 16, k16, lane);
                }
#pragma unroll
                for (int i = 0; i < 4; i++)
#pragma unroll
                    for (int j = 0; j < 4; j++) {
                        uint32_t B0h = bh[j >> 1][(j & 1) * 2], B1h = bh[j >> 1][(j & 1) * 2 + 1];
                        uint32_t B0l = bl[j >> 1][(j & 1) * 2], B1l = bl[j >> 1][(j & 1) * 2 + 1];
                        mma16816(c[i][j], ah[i], B0h, B1h);
                        mma16816(c[i][j], al[i], B0h, B1h);
                        mma16816(c[i][j], ah[i], B0l, B1l);
                    }
            }
        }

        // per-block gate epilogue (thread-local stage mapping, no extra sync needed)
#pragma unroll
        for (int i = 0; i < 4; i++)
#pragma unroll
            for (int j = 0; j < 4; j++) {
                int mA = wm * 64 + i * 16 + (lane >> 2);
                int col = wn * 32 + j * 8 + (lane & 3) * 2;
#pragma unroll
                for (int half = 0; half < 2; half++) {
                    int rr = mA + half * 8;
                    size_t grow = (size_t)(m0 + rr);
                    float v0 = c[i][j][half * 2]     + __ldg(&b_hh[b * 128 + col]);
                    float v1 = c[i][j][half * 2 + 1] + __ldg(&b_hh[b * 128 + col + 1]);
                    float gi0 = __ldg(&g_gi[grow * 384 + b * 128 + col]);
                    float gi1 = __ldg(&g_gi[grow * 384 + b * 128 + col + 1]);
                    if (b == 0) {
                        str_[rr * 129 + col]     = sigm(gi0 + v0);
                        str_[rr * 129 + col + 1] = sigm(gi1 + v1);
                    } else if (b == 1) {
                        stz_[rr * 129 + col]     = sigm(gi0 + v0);
                        stz_[rr * 129 + col + 1] = sigm(gi1 + v1);
                    } else {
                        float r0 = str_[rr * 129 + col], r1 = str_[rr * 129 + col + 1];
                        str_[rr * 129 + col]     = tanhf(gi0 + r0 * v0);
                        str_[rr * 129 + col + 1] = tanhf(gi1 + r1 * v1);
                    }
                }
            }
    }
    __syncthreads();

    // final combine + coalesced write of h and its bf16 hi/lo split
#pragma unroll
    for (int it = 0; it < 64; it++) {
        int idx = tid + 256 * it;
        int row = idx >> 7, col = idx & 127;
        size_t gidx = ((size_t)m0 + row) * 128 + col;
        float n = str_[row * 129 + col];
        float z = stz_[row * 129 + col];
        float hold = g_h[gidx];
        float hv = (1.f - z) * n + z * hold;
        g_h[gidx] = hv;
        __nv_bfloat16 hi = __float2bfloat16(hv);
        g_h_hi[gidx] = hi;
        g_h_lo[gidx] = __float2bfloat16(hv - __bfloat162float(hi));
    }
}

// ---------------- utility kernels ----------------
__global__ void copy4_kernel(float4* __restrict__ dst, const float4* __restrict__ src, int n4) {
    int i = blockIdx.x * blockDim.x + threadIdx.x;
    if (i < n4) dst[i] = src[i];
}
__global__ void zero4_kernel(float4* __restrict__ dst, int n4) {
    int i = blockIdx.x * blockDim.x + threadIdx.x;
    if (i < n4) dst[i] = make_float4(0.f, 0.f, 0.f, 0.f);
}
__global__ void detect_kernel(const unsigned int* __restrict__ p) {
    if (blockIdx.x == 0 && threadIdx.x == 0) {
        unsigned long long s = 0;
        for (int i = 1; i < 2048; i += 2) s += p[i];
        g_is64 = (s == 0ull) ? 1 : 0;
    }
}
__global__ void conv_edges_kernel(const int* __restrict__ p) {
    int i = blockIdx.x * blockDim.x + threadIdx.x;
    if (i >= EE) return;
    if (g_is64) { g_src[i] = p[2 * i]; g_dst[i] = p[2 * (EE + i)]; }
    else        { g_src[i] = p[i];     g_dst[i] = p[EE + i]; }
}
__global__ void conv_split4_kernel(const float4* __restrict__ src,
                                   __nv_bfloat162* __restrict__ hi,
                                   __nv_bfloat162* __restrict__ lo, int n4) {
    int i = blockIdx.x * blockDim.x + threadIdx.x;
    if (i >= n4) return;
    float4 v = src[i];
    __nv_bfloat16 h0 = __float2bfloat16(v.x), h1 = __float2bfloat16(v.y);
    __nv_bfloat16 h2 = __float2bfloat16(v.z), h3 = __float2bfloat16(v.w);
    __nv_bfloat162 a, b;
    a.x = h0; a.y = h1; hi[2 * i] = a;
    b.x = h2; b.y = h3; hi[2 * i + 1] = b;
    a.x = __float2bfloat16(v.x - __bfloat162float(h0));
    a.y = __float2bfloat16(v.y - __bfloat162float(h1));
    lo[2 * i] = a;
    b.x = __float2bfloat16(v.z - __bfloat162float(h2));
    b.y = __float2bfloat16(v.w - __bfloat162float(h3));
    lo[2 * i + 1] = b;
}
__global__ void transconvW_kernel(const float* __restrict__ Wl) {
    int i = blockIdx.x * blockDim.x + threadIdx.x;
    if (i >= 128 * 128) return;
    int k = i >> 7, j = i & 127;
    float v = Wl[i];
    __nv_bfloat16 h = __float2bfloat16(v);
    g_Wt_hi[j * 128 + k] = h;
    g_Wt_lo[j * 128 + k] = __float2bfloat16(v - __bfloat162float(h));
}

// ---------------- edge scatter: one warp per edge ----------------
__global__ void scatter_kernel(const float* __restrict__ ea) {
    int gw = (blockIdx.x * blockDim.x + threadIdx.x) >> 5;
    int lane = threadIdx.x & 31;
    if (gw >= EE) return;
    int s = g_src[gw];
    int d = g_dst[gw];
    float w = __ldg(&ea[gw]);
    float4 v = *((const float4*)g_m + (size_t)s * 32 + lane);
    v.x *= w; v.y *= w; v.z *= w; v.w *= w;
    float* dp = g_agg + (size_t)d * 128 + lane * 4;
    asm volatile("red.global.add.v4.f32 [%0], {%1, %2, %3, %4};"
                 :: "l"(dp), "f"(v.x), "f"(v.y), "f"(v.z), "f"(v.w) : "memory");
}

// ---------------- launch ----------------
extern "C" void kernel_launch(void* const* d_in, const int* in_sizes, int n_in,
                              void* d_out, int out_size) {
    const float* x    = (const float*)d_in[0];
    const int*   ei   = (const int*)d_in[1];
    const float* ea   = (const float*)d_in[2];
    const float* W    = (const float*)d_in[3];
    const float* W_ih = (const float*)d_in[4];
    const float* W_hh = (const float*)d_in[5];
    const float* b_ih = (const float*)d_in[6];
    const float* b_hh = (const float*)d_in[7];
    float* out = (float*)d_out;

    cudaFuncSetAttribute(mgemm_kernel, cudaFuncAttributeMaxDynamicSharedMemorySize, SMEM_G);
    cudaFuncSetAttribute(gi_kernel,    cudaFuncAttributeMaxDynamicSharedMemorySize, SMEM_G);
    cudaFuncSetAttribute(ghgru_kernel, cudaFuncAttributeMaxDynamicSharedMemorySize, SMEM_B2);

    float *ph, *pagg;
    __nv_bfloat16 *phh, *phl, *pah, *pal, *pih, *pil, *pwh, *pwl;
    cudaGetSymbolAddress((void**)&ph,   g_h);
    cudaGetSymbolAddress((void**)&pagg, g_agg);
    cudaGetSymbolAddress((void**)&phh,  g_h_hi);
    cudaGetSymbolAddress((void**)&phl,  g_h_lo);
    cudaGetSymbolAddress((void**)&pah,  g_agg_hi);
    cudaGetSymbolAddress((void**)&pal,  g_agg_lo);
    cudaGetSymbolAddress((void**)&pih,  g_Wih_hi);
    cudaGetSymbolAddress((void**)&pil,  g_Wih_lo);
    cudaGetSymbolAddress((void**)&pwh,  g_Whh_hi);
    cudaGetSymbolAddress((void**)&pwl,  g_Whh_lo);

    const int n4 = ND / 4;  // 3.2M

    detect_kernel<<<1, 32>>>((const unsigned int*)ei);
    conv_edges_kernel<<<EE / 256, 256>>>(ei);
    copy4_kernel<<<n4 / 256, 256>>>((float4*)ph, (const float4*)x, n4);
    conv_split4_kernel<<<(n4 + 255) / 256, 256>>>((const float4*)x, (__nv_bfloat162*)phh, (__nv_bfloat162*)phl, n4);
    conv_split4_kernel<<<48, 256>>>((const float4*)W_ih, (__nv_bfloat162*)pih, (__nv_bfloat162*)pil, 384 * 128 / 4);
    conv_split4_kernel<<<48, 256>>>((const float4*)W_hh, (__nv_bfloat162*)pwh, (__nv_bfloat162*)pwl, 384 * 128 / 4);

    for (int l = 0; l < 3; l++) {
        transconvW_kernel<<<64, 256>>>(W + l * 128 * 128);
        mgemm_kernel<<<MBLK, 256, SMEM_G>>>();
        zero4_kernel<<<n4 / 256, 256>>>((float4*)pagg, n4);
        scatter_kernel<<<(EE * 32) / 256, 256>>>(ea);
        conv_split4_kernel<<<(n4 + 255) / 256, 256>>>((const float4*)pagg, (__nv_bfloat162*)pah, (__nv_bfloat162*)pal, n4);
        gi_kernel<<<dim3(MBLK, 3), 256, SMEM_G>>>(b_ih);
        ghgru_kernel<<<MBLK, 256, SMEM_B2>>>(b_hh);
    }

    copy4_kernel<<<n4 / 256, 256>>>((float4*)out, (const float4*)ph, n4);
}

// round 13
// speedup vs baseline: 1.2245x; 1.2245x over previous
#include <cuda_runtime.h>
#include <cstdint>

#define NN 100000
#define DD 128
#define EE 1600000
#define ND (NN * DD)
#define MBLK 782

// ---------------- scratch ----------------
__device__ float g_h[ND];
__device__ float g_agg[ND];
__device__ float g_gi[NN * 384];
__device__ float g_gh[NN * 384];
__device__ float g_M[3 * 384 * 128];   // M_l[j][t] = sum_k W_ih[j,k] * W_l[t,k]
__device__ int   g_src[EE];
__device__ int   g_dst[EE];
__device__ int   g_esrc[EE];
__device__ float g_ew[EE];
__device__ int   g_deg[NN];
__device__ int   g_eoff[NN + 1];
__device__ int   g_epos[NN];
__device__ int   g_is64;

// ---------------- f32x2 helpers ----------------
__device__ __forceinline__ unsigned long long pack2(float x, float y) {
    unsigned long long r;
    asm("mov.b64 %0, {%1, %2};" : "=l"(r) : "f"(x), "f"(y));
    return r;
}
__device__ __forceinline__ void fma2(unsigned long long& d, unsigned long long a, unsigned long long b) {
    asm("fma.rn.f32x2 %0, %1, %2, %0;" : "+l"(d) : "l"(a), "l"(b));
}
__device__ __forceinline__ float2 unpack2(unsigned long long v) {
    float2 f;
    asm("mov.b64 {%0, %1}, %2;" : "=f"(f.x), "=f"(f.y) : "l"(v));
    return f;
}

// ---------------- utility kernels ----------------
__global__ void copy4_kernel(float4* __restrict__ dst, const float4* __restrict__ src, int n4) {
    int i = blockIdx.x * blockDim.x + threadIdx.x;
    if (i < n4) dst[i] = src[i];
}
__global__ void detect_kernel(const unsigned int* __restrict__ p) {
    if (blockIdx.x == 0 && threadIdx.x == 0) {
        unsigned long long s = 0;
        for (int i = 1; i < 2048; i += 2) s += p[i];
        g_is64 = (s == 0ull) ? 1 : 0;
    }
}
__global__ void conv_edges_kernel(const int* __restrict__ p) {
    int i = blockIdx.x * blockDim.x + threadIdx.x;
    if (i >= EE) return;
    if (g_is64) { g_src[i] = p[2 * i]; g_dst[i] = p[2 * (EE + i)]; }
    else        { g_src[i] = p[i];     g_dst[i] = p[EE + i]; }
}

// ---------------- CSR build (per call; edges are call-constant) ----------------
__global__ void zero_deg_kernel() {
    int i = blockIdx.x * blockDim.x + threadIdx.x;
    if (i < NN) g_deg[i] = 0;
}
__global__ void hist_kernel() {
    int i = blockIdx.x * blockDim.x + threadIdx.x;
    if (i < EE) atomicAdd(&g_deg[g_dst[i]], 1);
}
// single-block two-level exclusive scan of g_deg -> g_eoff / g_epos
__global__ void scan_kernel() {
    __shared__ int ssum[256];
    int t = threadIdx.x;
    int b = t * 392;
    int e = min(b + 392, NN);
    int s = 0;
    for (int n = b; n < e; n++) s += g_deg[n];
    ssum[t] = s;
    __syncthreads();
    if (t == 0) {
        int run = 0;
        for (int i = 0; i < 256; i++) { int v = ssum[i]; ssum[i] = run; run += v; }
    }
    __syncthreads();
    int run = ssum[t];
    for (int n = b; n < e; n++) {
        g_eoff[n] = run;
        g_epos[n] = run;
        run += g_deg[n];
    }
    if (t == 255) g_eoff[NN] = run;
}
__global__ void fill_kernel(const float* __restrict__ ea) {
    int i = blockIdx.x * blockDim.x + threadIdx.x;
    if (i >= EE) return;
    int d = g_dst[i];
    int slot = atomicAdd(&g_epos[d], 1);
    g_esrc[slot] = g_src[i];
    g_ew[slot] = ea[i];
}

// ---------------- M_l = W_ih @ W_l^T : M[l][j][t] = sum_k W_ih[j,k] W_l[t,k] ----------------
__global__ void mcomb_kernel(const float* __restrict__ W, const float* __restrict__ W_ih) {
    int idx = blockIdx.x * blockDim.x + threadIdx.x;
    if (idx >= 384 * 128) return;
    int l = blockIdx.y;
    int j = idx >> 7, t = idx & 127;
    const float* wi = W_ih + j * 128;
    const float* wl = W + l * 128 * 128 + t * 128;
    float s = 0.f;
#pragma unroll 8
    for (int k = 0; k < 128; k++) s = fmaf(__ldg(&wi[k]), __ldg(&wl[k]), s);
    g_M[(l * 384 + j) * 128 + t] = s;
}

// ---------------- gather: agg[n] = sum_{e: dst=n} h[src_e] * w_e  (warp per node) ----------------
__global__ void gather_kernel() {
    int gw = (blockIdx.x * blockDim.x + threadIdx.x) >> 5;
    int lane = threadIdx.x & 31;
    if (gw >= NN) return;
    int beg = g_eoff[gw], end = g_eoff[gw + 1];
    float4 acc = make_float4(0.f, 0.f, 0.f, 0.f);
    for (int e = beg; e < end; e++) {
        int s = __ldg(&g_esrc[e]);
        float w = __ldg(&g_ew[e]);
        float4 v = *((const float4*)g_h + (size_t)s * 32 + lane);
        acc.x = fmaf(v.x, w, acc.x);
        acc.y = fmaf(v.y, w, acc.y);
        acc.z = fmaf(v.z, w, acc.z);
        acc.w = fmaf(v.w, w, acc.w);
    }
    *((float4*)g_agg + (size_t)gw * 32 + lane) = acc;
}

// ---------------- GEMM: C[m, j0+j] = sum_k A[m,k] * Bt[(j0+j)*128 + k] + bias[j] ----------------
// R2-proven mapping; B stored pre-duplicated as (b,b) u64 pairs to kill the pack movs.
__launch_bounds__(256)
__global__ void gemm_bt_kernel(const float* __restrict__ A, const float* __restrict__ Bt,
                               const float* __restrict__ bias, float* __restrict__ C,
                               int M, int ldc) {
    __shared__ float As[16][132];
    __shared__ unsigned long long Bsd[16][132];

    const int m0  = blockIdx.x * 128;
    const int j0  = blockIdx.y * 128;
    const int tid = threadIdx.x;
    const int tx  = tid & 15;
    const int ty  = tid >> 4;

    const int lm = tid >> 1;
    const int l0 = ((tid * 2) & 3) * 4;   // 0 or 8

    unsigned long long acc[8][4];
#pragma unroll
    for (int jj = 0; jj < 8; jj++) {
        float bj = bias ? __ldg(&bias[j0 + tx + 16 * jj]) : 0.f;
        unsigned long long b2 = pack2(bj, bj);
#pragma unroll
        for (int p = 0; p < 4; p++) acc[jj][p] = b2;
    }

    const bool arow_ok = (m0 + lm) < M;
    const float* Arow = A + (size_t)(m0 + lm) * 128;
    const float* Brow = Bt + (size_t)(j0 + lm) * 128;
    const float4 zf4 = make_float4(0.f, 0.f, 0.f, 0.f);

    float4 a0 = arow_ok ? *(const float4*)&Arow[l0]     : zf4;
    float4 a1 = arow_ok ? *(const float4*)&Arow[l0 + 4] : zf4;
    float4 b0 = *(const float4*)&Brow[l0];
    float4 b1 = *(const float4*)&Brow[l0 + 4];

    for (int c = 0; c < 8; c++) {
        __syncthreads();
        As[l0 + 0][lm] = a0.x; As[l0 + 1][lm] = a0.y; As[l0 + 2][lm] = a0.z; As[l0 + 3][lm] = a0.w;
        As[l0 + 4][lm] = a1.x; As[l0 + 5][lm] = a1.y; As[l0 + 6][lm] = a1.z; As[l0 + 7][lm] = a1.w;
        Bsd[l0 + 0][lm] = pack2(b0.x, b0.x); Bsd[l0 + 1][lm] = pack2(b0.y, b0.y);
        Bsd[l0 + 2][lm] = pack2(b0.z, b0.z); Bsd[l0 + 3][lm] = pack2(b0.w, b0.w);
        Bsd[l0 + 4][lm] = pack2(b1.x, b1.x); Bsd[l0 + 5][lm] = pack2(b1.y, b1.y);
        Bsd[l0 + 6][lm] = pack2(b1.z, b1.z); Bsd[l0 + 7][lm] = pack2(b1.w, b1.w);
        __syncthreads();

        if (c < 7) {
            int kn = (c + 1) * 16;
            a0 = arow_ok ? *(const float4*)&Arow[kn + l0]     : zf4;
            a1 = arow_ok ? *(const float4*)&Arow[kn + l0 + 4] : zf4;
            b0 = *(const float4*)&Brow[kn + l0];
            b1 = *(const float4*)&Brow[kn + l0 + 4];
        }

#pragma unroll
        for (int kk = 0; kk < 16; kk++) {
            ulonglong2 pa0 = *(const ulonglong2*)&As[kk][ty * 8];
            ulonglong2 pa1 = *(const ulonglong2*)&As[kk][ty * 8 + 4];
            unsigned long long ap0 = pa0.x, ap1 = pa0.y, ap2 = pa1.x, ap3 = pa1.y;
#pragma unroll
            for (int jj = 0; jj < 8; jj++) {
                unsigned long long b2 = Bsd[kk][tx + 16 * jj];
                fma2(acc[jj][0], ap0, b2);
                fma2(acc[jj][1], ap1, b2);
                fma2(acc[jj][2], ap2, b2);
                fma2(acc[jj][3], ap3, b2);
            }
        }
    }

#pragma unroll
    for (int jj = 0; jj < 8; jj++) {
        int col = j0 + tx + 16 * jj;
#pragma unroll
        for (int p = 0; p < 4; p++) {
            float2 v = unpack2(acc[jj][p]);
            int r0 = m0 + ty * 8 + 2 * p;
            if (r0 < M)     C[(size_t)r0 * ldc + col]       = v.x;
            if (r0 + 1 < M) C[(size_t)(r0 + 1) * ldc + col] = v.y;
        }
    }
}

// ---------------- GRU gate elementwise ----------------
__global__ void gru_kernel(float* __restrict__ h) {
    int i = blockIdx.x * blockDim.x + threadIdx.x;
    if (i >= ND) return;
    int n = i >> 7, j = i & 127;
    const float* gi = g_gi + (size_t)n * 384;
    const float* gh = g_gh + (size_t)n * 384;
    float i_r = gi[j], i_z = gi[128 + j], i_n = gi[256 + j];
    float h_r = gh[j], h_z = gh[128 + j], h_n = gh[256 + j];
    float r = 1.f / (1.f + expf(-(i_r + h_r)));
    float z = 1.f / (1.f + expf(-(i_z + h_z)));
    float nn = tanhf(i_n + r * h_n);
    float hv = h[i];
    h[i] = (1.f - z) * nn + z * hv;
}

// ---------------- launch ----------------
extern "C" void kernel_launch(void* const* d_in, const int* in_sizes, int n_in,
                              void* d_out, int out_size) {
    const float* x    = (const float*)d_in[0];
    const int*   ei   = (const int*)d_in[1];
    const float* ea   = (const float*)d_in[2];
    const float* W    = (const float*)d_in[3];
    const float* W_ih = (const float*)d_in[4];
    const float* W_hh = (const float*)d_in[5];
    const float* b_ih = (const float*)d_in[6];
    const float* b_hh = (const float*)d_in[7];
    float* out = (float*)d_out;

    float *ph, *pagg, *pgi, *pgh, *pM;
    cudaGetSymbolAddress((void**)&ph,   g_h);
    cudaGetSymbolAddress((void**)&pagg, g_agg);
    cudaGetSymbolAddress((void**)&pgi,  g_gi);
    cudaGetSymbolAddress((void**)&pgh,  g_gh);
    cudaGetSymbolAddress((void**)&pM,   g_M);

    const int n4 = ND / 4;

    detect_kernel<<<1, 32>>>((const unsigned int*)ei);
    conv_edges_kernel<<<EE / 256, 256>>>(ei);
    copy4_kernel<<<n4 / 256, 256>>>((float4*)ph, (const float4*)x, n4);

    // CSR build (once per call)
    zero_deg_kernel<<<(NN + 255) / 256, 256>>>();
    hist_kernel<<<EE / 256, 256>>>();
    scan_kernel<<<1, 256>>>();
    fill_kernel<<<EE / 256, 256>>>(ea);

    // combined weights M_l = W_ih @ W_l^T for all layers
    mcomb_kernel<<<dim3(192, 3), 256>>>(W, W_ih);

    for (int l = 0; l < 3; l++) {
        gather_kernel<<<(NN * 32 + 255) / 256, 256>>>();
        gemm_bt_kernel<<<dim3(MBLK, 3), 256>>>(pagg, pM + l * 384 * 128, b_ih, pgi, NN, 384);
        gemm_bt_kernel<<<dim3(MBLK, 3), 256>>>(ph, W_hh, b_hh, pgh, NN, 384);
        gru_kernel<<<(ND + 255) / 256, 256>>>(ph);
    }

    copy4_kernel<<<n4 / 256, 256>>>((float4*)out, (const float4*)ph, n4);
}